// round 5
// baseline (speedup 1.0000x reference)
#include <cuda_runtime.h>
#include <cuda_bf16.h>
#include <cstdint>

#define MAX_NU 160000
#define MAX_NM 60000
#define MAX_E  5000000
#define DIM 64
#define COEF (13.0f / 12.0f)   // 1/2 + 1/3 + 1/4 : all layers aggregate layer-0 feats

#define SCAN_TILE 2048          // elements per scan block (256 threads x 8)

// ---- scratch (static device globals; no allocation allowed) ----------------
__device__ int   g_deg_u[MAX_NU];
__device__ int   g_deg_m[MAX_NM];
__device__ float g_inv_u[MAX_NU];
__device__ float g_inv_m[MAX_NM];
__device__ int   g_off_u[MAX_NU + 1];
__device__ int   g_off_m[MAX_NM + 1];
__device__ int   g_cur_u[MAX_NU];
__device__ int   g_cur_m[MAX_NM];
__device__ int   g_nbr_u[MAX_E];    // per user: movie neighbors
__device__ int   g_nbr_m[MAX_E];    // per movie: user neighbors
__device__ int   g_bsum_u[256];
__device__ int   g_bsum_m[128];
// bf16 staged source rows, PRE-SCALED by inv_src. Row = 64 bf16 = 32 words.
__device__ unsigned g_xm_bf[MAX_NM * 32];   // 7.68 MB
__device__ unsigned g_xu_bf[MAX_NU * 32];   // 20.5 MB

// ---------------------------------------------------------------------------
__global__ void k_zero_deg(int nu, int nm) {
    int i = blockIdx.x * blockDim.x + threadIdx.x;
    if (i < nu) g_deg_u[i] = 0;
    if (i < nm) g_deg_m[i] = 0;
}

__global__ void k_count_deg(const int* __restrict__ ef, const int* __restrict__ et, int E) {
    int i = blockIdx.x * blockDim.x + threadIdx.x;
    int stride = gridDim.x * blockDim.x;
    for (; i < E; i += stride) {
        atomicAdd(&g_deg_m[ef[i]], 1);
        atomicAdd(&g_deg_u[et[i]], 1);
    }
}

// ---- parallel exclusive scan, 3 phases -------------------------------------
__global__ void k_scan_part(int nu, int nm, int Bu) {
    __shared__ int sh[256];
    int b = blockIdx.x;
    const int* deg; int* off; int* bsum; int n; int lb;
    if (b < Bu) { deg = g_deg_u; off = g_off_u; bsum = g_bsum_u; n = nu; lb = b; }
    else        { deg = g_deg_m; off = g_off_m; bsum = g_bsum_m; n = nm; lb = b - Bu; }

    int t = threadIdx.x;
    int idx = lb * SCAN_TILE + t * 8;
    int v[8], s = 0;
    #pragma unroll
    for (int j = 0; j < 8; j++) {
        v[j] = (idx + j < n) ? deg[idx + j] : 0;
        s += v[j];
    }
    sh[t] = s;
    __syncthreads();
    #pragma unroll
    for (int o = 1; o < 256; o <<= 1) {
        int tmp = (t >= o) ? sh[t - o] : 0;
        __syncthreads();
        sh[t] += tmp;
        __syncthreads();
    }
    int ex = sh[t] - s;
    #pragma unroll
    for (int j = 0; j < 8; j++) {
        if (idx + j < n) off[idx + j] = ex;
        ex += v[j];
    }
    if (t == 255) bsum[lb] = sh[255];
}

__global__ void k_scan_bsum(int Bu, int Bm, int nu, int nm) {
    if (threadIdx.x == 0) {
        int acc = 0;
        for (int i = 0; i < Bu; i++) { int v = g_bsum_u[i]; g_bsum_u[i] = acc; acc += v; }
        g_off_u[nu] = acc;
    }
    if (threadIdx.x == 1) {
        int acc = 0;
        for (int i = 0; i < Bm; i++) { int v = g_bsum_m[i]; g_bsum_m[i] = acc; acc += v; }
        g_off_m[nm] = acc;
    }
}

__global__ void k_scan_add(int nu, int nm, int Bu) {
    int b = blockIdx.x;
    const int* deg; int* off; int* cur; float* inv; const int* bsum; int n; int lb;
    if (b < Bu) { deg = g_deg_u; off = g_off_u; cur = g_cur_u; inv = g_inv_u; bsum = g_bsum_u; n = nu; lb = b; }
    else        { deg = g_deg_m; off = g_off_m; cur = g_cur_m; inv = g_inv_m; bsum = g_bsum_m; n = nm; lb = b - Bu; }

    int add = bsum[lb];
    int idx = lb * SCAN_TILE + threadIdx.x * 8;
    #pragma unroll
    for (int j = 0; j < 8; j++) {
        int i = idx + j;
        if (i < n) {
            int o = off[i] + add;
            off[i] = o;
            cur[i] = o;
            int d = deg[i];
            inv[i] = (d > 0) ? rsqrtf((float)d) : 0.0f;
        }
    }
}

// ---- convert: stage pre-scaled bf16 rows -----------------------------------
// thread handles one float4 chunk (4 dims = 2 words) of one node row.
__global__ void k_convert(const float4* __restrict__ xu, const float4* __restrict__ xm,
                          int nu, int nm) {
    int i = blockIdx.x * blockDim.x + threadIdx.x;
    int total_u = nu * 16;
    int total   = total_u + nm * 16;
    if (i >= total) return;
    const float4* src; const float* inv; unsigned* dst; int node, chunk;
    if (i < total_u) { src = xu; inv = g_inv_u; dst = g_xu_bf; node = i >> 4; chunk = i & 15; }
    else { int j = i - total_u; src = xm; inv = g_inv_m; dst = g_xm_bf; node = j >> 4; chunk = j & 15; }

    float sc = inv[node];
    float4 v = src[node * 16 + chunk];
    __nv_bfloat162 b0 = __floats2bfloat162_rn(sc * v.x, sc * v.y);
    __nv_bfloat162 b1 = __floats2bfloat162_rn(sc * v.z, sc * v.w);
    uint2 p;
    p.x = *(unsigned int*)&b0;
    p.y = *(unsigned int*)&b1;
    *(uint2*)&dst[node * 32 + chunk * 2] = p;
}

// ---- CSR fill --------------------------------------------------------------
__global__ void k_fill(const int* __restrict__ ef, const int* __restrict__ et, int E) {
    int i = blockIdx.x * blockDim.x + threadIdx.x;
    int stride = gridDim.x * blockDim.x;
    for (; i < E; i += stride) {
        int f = ef[i];   // movie
        int t = et[i];   // user
        int pu = atomicAdd(&g_cur_u[t], 1);
        g_nbr_u[pu] = f;
        int pm = atomicAdd(&g_cur_m[f], 1);
        g_nbr_m[pm] = t;
    }
}

// ---- merged gather: one warp per node, lane owns 2 dims --------------------
// Source rows are pre-scaled bf16 (32 words). Each lane loads 1 word/neighbor;
// bf16->f32 is an exact bit shift (no cvt). 4x unroll, 8 accumulators.
// out[node] = x_self + COEF * inv_self * sum_f staged_src[f]
__global__ void __launch_bounds__(256)
k_gather_all(const float2* __restrict__ xu2, const float2* __restrict__ xm2,
             float2* __restrict__ ru2, float2* __restrict__ rm2,
             int nu, int nm)
{
    int gtid = blockIdx.x * blockDim.x + threadIdx.x;
    int w = gtid >> 5;
    if (w >= nu + nm) return;
    int lane = threadIdx.x & 31;

    const int* nbr; const int* roff; const unsigned* src;
    const float2* xself; const float* inv_self; float2* out; int node;
    if (w < nu) {
        node = w; nbr = g_nbr_u; roff = g_off_u; src = g_xm_bf;
        xself = xu2; inv_self = g_inv_u; out = ru2;
    } else {
        node = w - nu; nbr = g_nbr_m; roff = g_off_m; src = g_xu_bf;
        xself = xm2; inv_self = g_inv_m; out = rm2;
    }

    int s = roff[node];
    int e = roff[node + 1];

    float a0 = 0.f, a1 = 0.f, b0 = 0.f, b1 = 0.f;
    float c0 = 0.f, c1 = 0.f, d0 = 0.f, d1 = 0.f;

    int i = s;
    for (; i + 4 <= e; i += 4) {
        int f0 = __ldg(&nbr[i + 0]);
        int f1 = __ldg(&nbr[i + 1]);
        int f2 = __ldg(&nbr[i + 2]);
        int f3 = __ldg(&nbr[i + 3]);
        unsigned p0 = __ldg(&src[f0 * 32 + lane]);
        unsigned p1 = __ldg(&src[f1 * 32 + lane]);
        unsigned p2 = __ldg(&src[f2 * 32 + lane]);
        unsigned p3 = __ldg(&src[f3 * 32 + lane]);
        a0 += __uint_as_float(p0 << 16);
        a1 += __uint_as_float(p0 & 0xFFFF0000u);
        b0 += __uint_as_float(p1 << 16);
        b1 += __uint_as_float(p1 & 0xFFFF0000u);
        c0 += __uint_as_float(p2 << 16);
        c1 += __uint_as_float(p2 & 0xFFFF0000u);
        d0 += __uint_as_float(p3 << 16);
        d1 += __uint_as_float(p3 & 0xFFFF0000u);
    }
    for (; i < e; i++) {
        int f = __ldg(&nbr[i]);
        unsigned p = __ldg(&src[f * 32 + lane]);
        a0 += __uint_as_float(p << 16);
        a1 += __uint_as_float(p & 0xFFFF0000u);
    }
    float lo = (a0 + b0) + (c0 + d0);
    float hi = (a1 + b1) + (c1 + d1);

    float2 xs = xself[node * 32 + lane];
    float c = COEF * inv_self[node];
    float2 r;
    r.x = fmaf(c, lo, xs.x);
    r.y = fmaf(c, hi, xs.y);
    out[node * 32 + lane] = r;
}

// ---- scores ----------------------------------------------------------------
__global__ void k_scores(const int* __restrict__ lm, const int* __restrict__ lu,
                         const float2* __restrict__ ru, const float2* __restrict__ rm,
                         float* __restrict__ out, int L) {
    int gtid = blockIdx.x * blockDim.x + threadIdx.x;
    int l    = gtid >> 5;
    int lane = threadIdx.x & 31;
    if (l >= L) return;

    int m = lm[l];
    int u = lu[l];
    float2 a = __ldg(&ru[u * 32 + lane]);
    float2 b = __ldg(&rm[m * 32 + lane]);
    float s = a.x * b.x + a.y * b.y;

    #pragma unroll
    for (int off = 16; off > 0; off >>= 1)
        s += __shfl_down_sync(0xFFFFFFFFu, s, off);

    if (lane == 0) out[l] = s;
}

// ---------------------------------------------------------------------------
extern "C" void kernel_launch(void* const* d_in, const int* in_sizes, int n_in,
                              void* d_out, int out_size) {
    const float* emb_user  = (const float*)d_in[0];   // [NU, 64]
    const float* emb_movie = (const float*)d_in[1];   // [NM, 64]
    const int* edge_from   = (const int*)d_in[4];     // [E] movie idx
    const int* edge_to     = (const int*)d_in[5];     // [E] user idx
    const int* label_movie = (const int*)d_in[6];     // [L]
    const int* label_user  = (const int*)d_in[7];     // [L]

    int NU = in_sizes[0] / DIM;
    int NM = in_sizes[1] / DIM;
    int E  = in_sizes[4];
    int L  = in_sizes[6];

    float* out    = (float*)d_out;
    float* scores = out;                    // [L]
    float* res_u  = out + L;                // [NU*64]
    float* res_m  = out + L + NU * DIM;     // [NM*64]

    int nmax = (NU > NM) ? NU : NM;
    int Bu = (NU + SCAN_TILE - 1) / SCAN_TILE;
    int Bm = (NM + SCAN_TILE - 1) / SCAN_TILE;

    k_zero_deg<<<(nmax + 255) / 256, 256>>>(NU, NM);
    k_count_deg<<<2048, 256>>>(edge_from, edge_to, E);
    k_scan_part<<<Bu + Bm, 256>>>(NU, NM, Bu);
    k_scan_bsum<<<1, 32>>>(Bu, Bm, NU, NM);
    k_scan_add<<<Bu + Bm, 256>>>(NU, NM, Bu);

    // stage pre-scaled bf16 rows (needs inv; independent of fill)
    {
        int total = (NU + NM) * 16;
        k_convert<<<(total + 255) / 256, 256>>>((const float4*)emb_user,
                                                (const float4*)emb_movie, NU, NM);
    }

    k_fill<<<2048, 256>>>(edge_from, edge_to, E);

    // merged gather (users + movies), one warp per node
    {
        long long threads = (long long)(NU + NM) * 32;
        int blocks = (int)((threads + 255) / 256);
        k_gather_all<<<blocks, 256>>>((const float2*)emb_user, (const float2*)emb_movie,
                                      (float2*)res_u, (float2*)res_m, NU, NM);
    }

    {
        long long threads = (long long)L * 32;
        int blocks = (int)((threads + 255) / 256);
        k_scores<<<blocks, 256>>>(label_movie, label_user,
                                  (const float2*)res_u, (const float2*)res_m,
                                  scores, L);
    }
}

// round 6
// speedup vs baseline: 1.1334x; 1.1334x over previous
#include <cuda_runtime.h>
#include <cuda_bf16.h>
#include <cstdint>

#define MAX_NU 160000
#define MAX_NM 60000
#define MAX_E  5000000
#define DIM 64
#define COEF (13.0f / 12.0f)   // 1/2 + 1/3 + 1/4 : all layers aggregate layer-0 feats

#define SCAN_TILE 2048          // elements per scan block (256 threads x 8)

// ---- scratch (static device globals; no allocation allowed) ----------------
__device__ int   g_deg_u[MAX_NU];
__device__ int   g_deg_m[MAX_NM];
__device__ float g_inv_u[MAX_NU];
__device__ float g_inv_m[MAX_NM];
__device__ int   g_off_u[MAX_NU + 1];
__device__ int   g_off_m[MAX_NM + 1];
__device__ int   g_cur_u[MAX_NU];
__device__ int   g_cur_m[MAX_NM];
__device__ int   g_nbr_u[MAX_E];    // per user: movie neighbors
__device__ int   g_nbr_m[MAX_E];    // per movie: user neighbors
__device__ int   g_bsum_u[256];
__device__ int   g_bsum_m[128];
// bf16 staged source rows, PRE-SCALED by inv_src. Row = 64 bf16 = 16 uint2.
__device__ uint2 g_xm_bf[MAX_NM * 16];   // 7.68 MB
__device__ uint2 g_xu_bf[MAX_NU * 16];   // 20.5 MB

// ---------------------------------------------------------------------------
__global__ void k_zero_deg(int nu, int nm) {
    int i = blockIdx.x * blockDim.x + threadIdx.x;
    if (i < nu) g_deg_u[i] = 0;
    if (i < nm) g_deg_m[i] = 0;
}

__global__ void k_count_deg(const int* __restrict__ ef, const int* __restrict__ et, int E) {
    int i = blockIdx.x * blockDim.x + threadIdx.x;
    int stride = gridDim.x * blockDim.x;
    for (; i < E; i += stride) {
        atomicAdd(&g_deg_m[ef[i]], 1);
        atomicAdd(&g_deg_u[et[i]], 1);
    }
}

// ---- parallel exclusive scan, 3 phases -------------------------------------
__global__ void k_scan_part(int nu, int nm, int Bu) {
    __shared__ int sh[256];
    int b = blockIdx.x;
    const int* deg; int* off; int* bsum; int n; int lb;
    if (b < Bu) { deg = g_deg_u; off = g_off_u; bsum = g_bsum_u; n = nu; lb = b; }
    else        { deg = g_deg_m; off = g_off_m; bsum = g_bsum_m; n = nm; lb = b - Bu; }

    int t = threadIdx.x;
    int idx = lb * SCAN_TILE + t * 8;
    int v[8], s = 0;
    #pragma unroll
    for (int j = 0; j < 8; j++) {
        v[j] = (idx + j < n) ? deg[idx + j] : 0;
        s += v[j];
    }
    sh[t] = s;
    __syncthreads();
    #pragma unroll
    for (int o = 1; o < 256; o <<= 1) {
        int tmp = (t >= o) ? sh[t - o] : 0;
        __syncthreads();
        sh[t] += tmp;
        __syncthreads();
    }
    int ex = sh[t] - s;
    #pragma unroll
    for (int j = 0; j < 8; j++) {
        if (idx + j < n) off[idx + j] = ex;
        ex += v[j];
    }
    if (t == 255) bsum[lb] = sh[255];
}

__global__ void k_scan_bsum(int Bu, int Bm, int nu, int nm) {
    if (threadIdx.x == 0) {
        int acc = 0;
        for (int i = 0; i < Bu; i++) { int v = g_bsum_u[i]; g_bsum_u[i] = acc; acc += v; }
        g_off_u[nu] = acc;
    }
    if (threadIdx.x == 1) {
        int acc = 0;
        for (int i = 0; i < Bm; i++) { int v = g_bsum_m[i]; g_bsum_m[i] = acc; acc += v; }
        g_off_m[nm] = acc;
    }
}

__global__ void k_scan_add(int nu, int nm, int Bu) {
    int b = blockIdx.x;
    const int* deg; int* off; int* cur; float* inv; const int* bsum; int n; int lb;
    if (b < Bu) { deg = g_deg_u; off = g_off_u; cur = g_cur_u; inv = g_inv_u; bsum = g_bsum_u; n = nu; lb = b; }
    else        { deg = g_deg_m; off = g_off_m; cur = g_cur_m; inv = g_inv_m; bsum = g_bsum_m; n = nm; lb = b - Bu; }

    int add = bsum[lb];
    int idx = lb * SCAN_TILE + threadIdx.x * 8;
    #pragma unroll
    for (int j = 0; j < 8; j++) {
        int i = idx + j;
        if (i < n) {
            int o = off[i] + add;
            off[i] = o;
            cur[i] = o;
            int d = deg[i];
            inv[i] = (d > 0) ? rsqrtf((float)d) : 0.0f;
        }
    }
}

// ---- convert: stage pre-scaled bf16 rows -----------------------------------
__global__ void k_convert(const float4* __restrict__ xu, const float4* __restrict__ xm,
                          int nu, int nm) {
    int i = blockIdx.x * blockDim.x + threadIdx.x;
    int total_u = nu * 16;
    int total   = total_u + nm * 16;
    if (i >= total) return;
    const float4* src; const float* inv; uint2* dst; int node, chunk;
    if (i < total_u) { src = xu; inv = g_inv_u; dst = g_xu_bf; node = i >> 4; chunk = i & 15; }
    else { int j = i - total_u; src = xm; inv = g_inv_m; dst = g_xm_bf; node = j >> 4; chunk = j & 15; }

    float sc = inv[node];
    float4 v = src[node * 16 + chunk];
    __nv_bfloat162 b0 = __floats2bfloat162_rn(sc * v.x, sc * v.y);
    __nv_bfloat162 b1 = __floats2bfloat162_rn(sc * v.z, sc * v.w);
    uint2 p;
    p.x = *(unsigned int*)&b0;
    p.y = *(unsigned int*)&b1;
    dst[node * 16 + chunk] = p;
}

// ---- CSR fill --------------------------------------------------------------
__global__ void k_fill(const int* __restrict__ ef, const int* __restrict__ et, int E) {
    int i = blockIdx.x * blockDim.x + threadIdx.x;
    int stride = gridDim.x * blockDim.x;
    for (; i < E; i += stride) {
        int f = ef[i];   // movie
        int t = et[i];   // user
        int pu = atomicAdd(&g_cur_u[t], 1);
        g_nbr_u[pu] = f;
        int pm = atomicAdd(&g_cur_m[f], 1);
        g_nbr_m[pm] = t;
    }
}

// ---- merged gather: one warp per node, half-warps over neighbors -----------
// R4 formulation (measured fastest) with 4x unroll per half (8 rows in flight
// per warp) and bit-shift bf16->f32 (no cvt ops).
// out[node] = x_self + COEF * inv_self * sum_f staged_src[f]
__device__ __forceinline__ void acc_word(float4& acc, uint2 p) {
    acc.x += __uint_as_float(p.x << 16);
    acc.y += __uint_as_float(p.x & 0xFFFF0000u);
    acc.z += __uint_as_float(p.y << 16);
    acc.w += __uint_as_float(p.y & 0xFFFF0000u);
}

__global__ void __launch_bounds__(256)
k_gather_all(const float4* __restrict__ xu, const float4* __restrict__ xm,
             float4* __restrict__ ru, float4* __restrict__ rm,
             int nu, int nm)
{
    int gtid = blockIdx.x * blockDim.x + threadIdx.x;
    int w = gtid >> 5;
    if (w >= nu + nm) return;
    int lane = threadIdx.x & 31;
    int half = lane >> 4;
    int l    = lane & 15;

    const int* nbr; const int* roff; const uint2* src;
    const float4* xself; const float* inv_self; float4* out; int node;
    if (w < nu) {
        node = w; nbr = g_nbr_u; roff = g_off_u; src = g_xm_bf;
        xself = xu; inv_self = g_inv_u; out = ru;
    } else {
        node = w - nu; nbr = g_nbr_m; roff = g_off_m; src = g_xu_bf;
        xself = xm; inv_self = g_inv_m; out = rm;
    }

    int s = roff[node];
    int e = roff[node + 1];

    float4 acc0 = make_float4(0.f, 0.f, 0.f, 0.f);
    float4 acc1 = make_float4(0.f, 0.f, 0.f, 0.f);
    float4 acc2 = make_float4(0.f, 0.f, 0.f, 0.f);
    float4 acc3 = make_float4(0.f, 0.f, 0.f, 0.f);

    int i = s + half;
    // 4 neighbors in flight per half-warp (8 per warp)
    for (; i + 6 < e; i += 8) {
        int f0 = __ldg(&nbr[i + 0]);
        int f1 = __ldg(&nbr[i + 2]);
        int f2 = __ldg(&nbr[i + 4]);
        int f3 = __ldg(&nbr[i + 6]);
        uint2 p0 = __ldg(&src[f0 * 16 + l]);
        uint2 p1 = __ldg(&src[f1 * 16 + l]);
        uint2 p2 = __ldg(&src[f2 * 16 + l]);
        uint2 p3 = __ldg(&src[f3 * 16 + l]);
        acc_word(acc0, p0);
        acc_word(acc1, p1);
        acc_word(acc2, p2);
        acc_word(acc3, p3);
    }
    for (; i < e; i += 2) {
        int f = __ldg(&nbr[i]);
        uint2 p = __ldg(&src[f * 16 + l]);
        acc_word(acc0, p);
    }
    acc0.x = (acc0.x + acc1.x) + (acc2.x + acc3.x);
    acc0.y = (acc0.y + acc1.y) + (acc2.y + acc3.y);
    acc0.z = (acc0.z + acc1.z) + (acc2.z + acc3.z);
    acc0.w = (acc0.w + acc1.w) + (acc2.w + acc3.w);

    __syncwarp();
    acc0.x += __shfl_xor_sync(0xFFFFFFFFu, acc0.x, 16);
    acc0.y += __shfl_xor_sync(0xFFFFFFFFu, acc0.y, 16);
    acc0.z += __shfl_xor_sync(0xFFFFFFFFu, acc0.z, 16);
    acc0.w += __shfl_xor_sync(0xFFFFFFFFu, acc0.w, 16);

    if (half == 0) {
        float4 xs = xself[node * 16 + l];
        float c = COEF * inv_self[node];
        float4 r;
        r.x = fmaf(c, acc0.x, xs.x);
        r.y = fmaf(c, acc0.y, xs.y);
        r.z = fmaf(c, acc0.z, xs.z);
        r.w = fmaf(c, acc0.w, xs.w);
        out[node * 16 + l] = r;
    }
}

// ---- scores ----------------------------------------------------------------
__global__ void k_scores(const int* __restrict__ lm, const int* __restrict__ lu,
                         const float2* __restrict__ ru, const float2* __restrict__ rm,
                         float* __restrict__ out, int L) {
    int gtid = blockIdx.x * blockDim.x + threadIdx.x;
    int l    = gtid >> 5;
    int lane = threadIdx.x & 31;
    if (l >= L) return;

    int m = lm[l];
    int u = lu[l];
    float2 a = __ldg(&ru[u * 32 + lane]);
    float2 b = __ldg(&rm[m * 32 + lane]);
    float s = a.x * b.x + a.y * b.y;

    #pragma unroll
    for (int off = 16; off > 0; off >>= 1)
        s += __shfl_down_sync(0xFFFFFFFFu, s, off);

    if (lane == 0) out[l] = s;
}

// ---------------------------------------------------------------------------
extern "C" void kernel_launch(void* const* d_in, const int* in_sizes, int n_in,
                              void* d_out, int out_size) {
    const float* emb_user  = (const float*)d_in[0];   // [NU, 64]
    const float* emb_movie = (const float*)d_in[1];   // [NM, 64]
    const int* edge_from   = (const int*)d_in[4];     // [E] movie idx
    const int* edge_to     = (const int*)d_in[5];     // [E] user idx
    const int* label_movie = (const int*)d_in[6];     // [L]
    const int* label_user  = (const int*)d_in[7];     // [L]

    int NU = in_sizes[0] / DIM;
    int NM = in_sizes[1] / DIM;
    int E  = in_sizes[4];
    int L  = in_sizes[6];

    float* out    = (float*)d_out;
    float* scores = out;                    // [L]
    float* res_u  = out + L;                // [NU*64]
    float* res_m  = out + L + NU * DIM;     // [NM*64]

    int nmax = (NU > NM) ? NU : NM;
    int Bu = (NU + SCAN_TILE - 1) / SCAN_TILE;
    int Bm = (NM + SCAN_TILE - 1) / SCAN_TILE;

    k_zero_deg<<<(nmax + 255) / 256, 256>>>(NU, NM);
    k_count_deg<<<2048, 256>>>(edge_from, edge_to, E);
    k_scan_part<<<Bu + Bm, 256>>>(NU, NM, Bu);
    k_scan_bsum<<<1, 32>>>(Bu, Bm, NU, NM);
    k_scan_add<<<Bu + Bm, 256>>>(NU, NM, Bu);

    // stage pre-scaled bf16 rows (needs inv; independent of fill)
    {
        int total = (NU + NM) * 16;
        k_convert<<<(total + 255) / 256, 256>>>((const float4*)emb_user,
                                                (const float4*)emb_movie, NU, NM);
    }

    k_fill<<<2048, 256>>>(edge_from, edge_to, E);

    // merged gather (users + movies), one warp per node
    {
        long long threads = (long long)(NU + NM) * 32;
        int blocks = (int)((threads + 255) / 256);
        k_gather_all<<<blocks, 256>>>((const float4*)emb_user, (const float4*)emb_movie,
                                      (float4*)res_u, (float4*)res_m, NU, NM);
    }

    {
        long long threads = (long long)L * 32;
        int blocks = (int)((threads + 255) / 256);
        k_scores<<<blocks, 256>>>(label_movie, label_user,
                                  (const float2*)res_u, (const float2*)res_m,
                                  scores, L);
    }
}

// round 7
// speedup vs baseline: 1.1999x; 1.0586x over previous
#include <cuda_runtime.h>
#include <cuda_bf16.h>
#include <cstdint>

#define MAX_NU 160000
#define MAX_NM 60000
#define MAX_E  5000000
#define DIM 64
#define COEF (13.0f / 12.0f)   // 1/2 + 1/3 + 1/4 : all layers aggregate layer-0 feats

#define SCAN_TILE 2048          // elements per scan block (256 threads x 8)

// ---- scratch (static device globals; no allocation allowed) ----------------
__device__ int   g_deg_u[MAX_NU];
__device__ int   g_deg_m[MAX_NM];
__device__ float g_inv_u[MAX_NU];
__device__ float g_inv_m[MAX_NM];
__device__ int   g_off_u[MAX_NU + 1];
__device__ int   g_off_m[MAX_NM + 1];
__device__ int   g_cur_u[MAX_NU];
__device__ int   g_cur_m[MAX_NM];
__device__ int   g_nbr_u[MAX_E];    // per user: movie neighbors
__device__ int   g_nbr_m[MAX_E];    // per movie: user neighbors
__device__ int   g_bsum_u[256];
__device__ int   g_bsum_m[128];
// bf16 staged source rows, PRE-SCALED by inv_src. Row = 64 bf16 = 16 uint2.
__device__ uint2 g_xm_bf[MAX_NM * 16];   // 7.68 MB
__device__ uint2 g_xu_bf[MAX_NU * 16];   // 20.5 MB

// ---------------------------------------------------------------------------
// count degrees: RED (no return), 2 edges per iteration
__global__ void k_count_deg(const int2* __restrict__ ef2, const int2* __restrict__ et2,
                            const int* __restrict__ ef, const int* __restrict__ et,
                            int E) {
    int E2 = E >> 1;
    int i = blockIdx.x * blockDim.x + threadIdx.x;
    int stride = gridDim.x * blockDim.x;
    for (; i < E2; i += stride) {
        int2 f = __ldg(&ef2[i]);
        int2 t = __ldg(&et2[i]);
        atomicAdd(&g_deg_m[f.x], 1);
        atomicAdd(&g_deg_m[f.y], 1);
        atomicAdd(&g_deg_u[t.x], 1);
        atomicAdd(&g_deg_u[t.y], 1);
    }
    // odd tail
    if (i == E2 && (E & 1)) {
        atomicAdd(&g_deg_m[ef[E - 1]], 1);
        atomicAdd(&g_deg_u[et[E - 1]], 1);
    }
}

// ---- parallel exclusive scan, 3 phases -------------------------------------
__global__ void k_scan_part(int nu, int nm, int Bu) {
    __shared__ int sh[256];
    int b = blockIdx.x;
    const int* deg; int* off; int* bsum; int n; int lb;
    if (b < Bu) { deg = g_deg_u; off = g_off_u; bsum = g_bsum_u; n = nu; lb = b; }
    else        { deg = g_deg_m; off = g_off_m; bsum = g_bsum_m; n = nm; lb = b - Bu; }

    int t = threadIdx.x;
    int idx = lb * SCAN_TILE + t * 8;
    int v[8], s = 0;
    #pragma unroll
    for (int j = 0; j < 8; j++) {
        v[j] = (idx + j < n) ? deg[idx + j] : 0;
        s += v[j];
    }
    sh[t] = s;
    __syncthreads();
    #pragma unroll
    for (int o = 1; o < 256; o <<= 1) {
        int tmp = (t >= o) ? sh[t - o] : 0;
        __syncthreads();
        sh[t] += tmp;
        __syncthreads();
    }
    int ex = sh[t] - s;
    #pragma unroll
    for (int j = 0; j < 8; j++) {
        if (idx + j < n) off[idx + j] = ex;
        ex += v[j];
    }
    if (t == 255) bsum[lb] = sh[255];
}

__global__ void k_scan_bsum(int Bu, int Bm, int nu, int nm) {
    if (threadIdx.x == 0) {
        int acc = 0;
        for (int i = 0; i < Bu; i++) { int v = g_bsum_u[i]; g_bsum_u[i] = acc; acc += v; }
        g_off_u[nu] = acc;
    }
    if (threadIdx.x == 1) {
        int acc = 0;
        for (int i = 0; i < Bm; i++) { int v = g_bsum_m[i]; g_bsum_m[i] = acc; acc += v; }
        g_off_m[nm] = acc;
    }
}

__global__ void k_scan_add(int nu, int nm, int Bu) {
    int b = blockIdx.x;
    const int* deg; int* off; int* cur; float* inv; const int* bsum; int n; int lb;
    if (b < Bu) { deg = g_deg_u; off = g_off_u; cur = g_cur_u; inv = g_inv_u; bsum = g_bsum_u; n = nu; lb = b; }
    else        { deg = g_deg_m; off = g_off_m; cur = g_cur_m; inv = g_inv_m; bsum = g_bsum_m; n = nm; lb = b - Bu; }

    int add = bsum[lb];
    int idx = lb * SCAN_TILE + threadIdx.x * 8;
    #pragma unroll
    for (int j = 0; j < 8; j++) {
        int i = idx + j;
        if (i < n) {
            int o = off[i] + add;
            off[i] = o;
            cur[i] = o;
            int d = deg[i];
            inv[i] = (d > 0) ? rsqrtf((float)d) : 0.0f;
        }
    }
}

// ---- convert: stage pre-scaled bf16 rows -----------------------------------
__global__ void k_convert(const float4* __restrict__ xu, const float4* __restrict__ xm,
                          int nu, int nm) {
    int i = blockIdx.x * blockDim.x + threadIdx.x;
    int total_u = nu * 16;
    int total   = total_u + nm * 16;
    if (i >= total) return;
    const float4* src; const float* inv; uint2* dst; int node, chunk;
    if (i < total_u) { src = xu; inv = g_inv_u; dst = g_xu_bf; node = i >> 4; chunk = i & 15; }
    else { int j = i - total_u; src = xm; inv = g_inv_m; dst = g_xm_bf; node = j >> 4; chunk = j & 15; }

    float sc = inv[node];
    float4 v = src[node * 16 + chunk];
    __nv_bfloat162 b0 = __floats2bfloat162_rn(sc * v.x, sc * v.y);
    __nv_bfloat162 b1 = __floats2bfloat162_rn(sc * v.z, sc * v.w);
    uint2 p;
    p.x = *(unsigned int*)&b0;
    p.y = *(unsigned int*)&b1;
    dst[node * 16 + chunk] = p;
}

// ---- CSR fill: 2-edge unroll, independent atomics --------------------------
__global__ void k_fill(const int2* __restrict__ ef2, const int2* __restrict__ et2,
                       const int* __restrict__ ef, const int* __restrict__ et, int E) {
    int E2 = E >> 1;
    int i = blockIdx.x * blockDim.x + threadIdx.x;
    int stride = gridDim.x * blockDim.x;
    for (; i < E2; i += stride) {
        int2 f = __ldg(&ef2[i]);
        int2 t = __ldg(&et2[i]);
        int pu0 = atomicAdd(&g_cur_u[t.x], 1);
        int pu1 = atomicAdd(&g_cur_u[t.y], 1);
        int pm0 = atomicAdd(&g_cur_m[f.x], 1);
        int pm1 = atomicAdd(&g_cur_m[f.y], 1);
        g_nbr_u[pu0] = f.x;
        g_nbr_u[pu1] = f.y;
        g_nbr_m[pm0] = t.x;
        g_nbr_m[pm1] = t.y;
    }
    if (i == E2 && (E & 1)) {
        int f = ef[E - 1], t = et[E - 1];
        int pu = atomicAdd(&g_cur_u[t], 1);
        g_nbr_u[pu] = f;
        int pm = atomicAdd(&g_cur_m[f], 1);
        g_nbr_m[pm] = t;
    }
}

// ---- merged gather: R4-exact structure, bit-shift bf16->f32 ----------------
// One warp per node; half-warps stride neighbors by 2, 2x unroll per half.
// out[node] = x_self + COEF * inv_self * sum_f staged_src[f]
__device__ __forceinline__ void acc_word(float4& acc, uint2 p) {
    acc.x += __uint_as_float(p.x << 16);
    acc.y += __uint_as_float(p.x & 0xFFFF0000u);
    acc.z += __uint_as_float(p.y << 16);
    acc.w += __uint_as_float(p.y & 0xFFFF0000u);
}

__global__ void __launch_bounds__(256)
k_gather_all(const float4* __restrict__ xu, const float4* __restrict__ xm,
             float4* __restrict__ ru, float4* __restrict__ rm,
             int nu, int nm)
{
    int gtid = blockIdx.x * blockDim.x + threadIdx.x;
    int w = gtid >> 5;
    if (w >= nu + nm) return;
    int lane = threadIdx.x & 31;
    int half = lane >> 4;
    int l    = lane & 15;

    const int* nbr; const int* roff; const uint2* src;
    const float4* xself; const float* inv_self; float4* out; int node;
    if (w < nu) {
        node = w; nbr = g_nbr_u; roff = g_off_u; src = g_xm_bf;
        xself = xu; inv_self = g_inv_u; out = ru;
    } else {
        node = w - nu; nbr = g_nbr_m; roff = g_off_m; src = g_xu_bf;
        xself = xm; inv_self = g_inv_m; out = rm;
    }

    int s = roff[node];
    int e = roff[node + 1];

    float4 acc0 = make_float4(0.f, 0.f, 0.f, 0.f);
    float4 acc1 = make_float4(0.f, 0.f, 0.f, 0.f);

    int i = s + half;
    for (; i + 2 < e; i += 4) {
        int f0 = __ldg(&nbr[i]);
        int f1 = __ldg(&nbr[i + 2]);
        uint2 p0 = __ldg(&src[f0 * 16 + l]);
        uint2 p1 = __ldg(&src[f1 * 16 + l]);
        acc_word(acc0, p0);
        acc_word(acc1, p1);
    }
    for (; i < e; i += 2) {
        int f = __ldg(&nbr[i]);
        uint2 p = __ldg(&src[f * 16 + l]);
        acc_word(acc0, p);
    }
    acc0.x += acc1.x; acc0.y += acc1.y; acc0.z += acc1.z; acc0.w += acc1.w;

    __syncwarp();
    acc0.x += __shfl_xor_sync(0xFFFFFFFFu, acc0.x, 16);
    acc0.y += __shfl_xor_sync(0xFFFFFFFFu, acc0.y, 16);
    acc0.z += __shfl_xor_sync(0xFFFFFFFFu, acc0.z, 16);
    acc0.w += __shfl_xor_sync(0xFFFFFFFFu, acc0.w, 16);

    if (half == 0) {
        float4 xs = xself[node * 16 + l];
        float c = COEF * inv_self[node];
        float4 r;
        r.x = fmaf(c, acc0.x, xs.x);
        r.y = fmaf(c, acc0.y, xs.y);
        r.z = fmaf(c, acc0.z, xs.z);
        r.w = fmaf(c, acc0.w, xs.w);
        out[node * 16 + l] = r;
    }
}

// ---- scores ----------------------------------------------------------------
__global__ void k_scores(const int* __restrict__ lm, const int* __restrict__ lu,
                         const float2* __restrict__ ru, const float2* __restrict__ rm,
                         float* __restrict__ out, int L) {
    int gtid = blockIdx.x * blockDim.x + threadIdx.x;
    int l    = gtid >> 5;
    int lane = threadIdx.x & 31;
    if (l >= L) return;

    int m = lm[l];
    int u = lu[l];
    float2 a = __ldg(&ru[u * 32 + lane]);
    float2 b = __ldg(&rm[m * 32 + lane]);
    float s = a.x * b.x + a.y * b.y;

    #pragma unroll
    for (int off = 16; off > 0; off >>= 1)
        s += __shfl_down_sync(0xFFFFFFFFu, s, off);

    if (lane == 0) out[l] = s;
}

// ---------------------------------------------------------------------------
extern "C" void kernel_launch(void* const* d_in, const int* in_sizes, int n_in,
                              void* d_out, int out_size) {
    const float* emb_user  = (const float*)d_in[0];   // [NU, 64]
    const float* emb_movie = (const float*)d_in[1];   // [NM, 64]
    const int* edge_from   = (const int*)d_in[4];     // [E] movie idx
    const int* edge_to     = (const int*)d_in[5];     // [E] user idx
    const int* label_movie = (const int*)d_in[6];     // [L]
    const int* label_user  = (const int*)d_in[7];     // [L]

    int NU = in_sizes[0] / DIM;
    int NM = in_sizes[1] / DIM;
    int E  = in_sizes[4];
    int L  = in_sizes[6];

    float* out    = (float*)d_out;
    float* scores = out;                    // [L]
    float* res_u  = out + L;                // [NU*64]
    float* res_m  = out + L + NU * DIM;     // [NM*64]

    int Bu = (NU + SCAN_TILE - 1) / SCAN_TILE;
    int Bm = (NM + SCAN_TILE - 1) / SCAN_TILE;

    // zero degree counters via memset nodes (no kernel launch needed)
    {
        void* p;
        cudaGetSymbolAddress(&p, g_deg_u);
        cudaMemsetAsync(p, 0, NU * sizeof(int));
        cudaGetSymbolAddress(&p, g_deg_m);
        cudaMemsetAsync(p, 0, NM * sizeof(int));
    }

    k_count_deg<<<2048, 256>>>((const int2*)edge_from, (const int2*)edge_to,
                               edge_from, edge_to, E);
    k_scan_part<<<Bu + Bm, 256>>>(NU, NM, Bu);
    k_scan_bsum<<<1, 32>>>(Bu, Bm, NU, NM);
    k_scan_add<<<Bu + Bm, 256>>>(NU, NM, Bu);

    // stage pre-scaled bf16 rows (needs inv; independent of fill)
    {
        int total = (NU + NM) * 16;
        k_convert<<<(total + 255) / 256, 256>>>((const float4*)emb_user,
                                                (const float4*)emb_movie, NU, NM);
    }

    k_fill<<<2048, 256>>>((const int2*)edge_from, (const int2*)edge_to,
                          edge_from, edge_to, E);

    // merged gather (users + movies), one warp per node
    {
        long long threads = (long long)(NU + NM) * 32;
        int blocks = (int)((threads + 255) / 256);
        k_gather_all<<<blocks, 256>>>((const float4*)emb_user, (const float4*)emb_movie,
                                      (float4*)res_u, (float4*)res_m, NU, NM);
    }

    {
        long long threads = (long long)L * 32;
        int blocks = (int)((threads + 255) / 256);
        k_scores<<<blocks, 256>>>(label_movie, label_user,
                                  (const float2*)res_u, (const float2*)res_m,
                                  scores, L);
    }
}